// round 4
// baseline (speedup 1.0000x reference)
#include <cuda_runtime.h>
#include <cstdint>

#define DI __device__ __forceinline__

static constexpr int NN  = 8192;
static constexpr int DIM = 256;

// ---------------- scratch (device globals; allocation forbidden) -----------
__device__ __align__(1024) float g_dis[NN];        // rsqrt(1 + rowsum(adj))
__device__ __align__(1024) float g_Mt[DIM * NN];   // M^T [n][j], tf32-rounded
__device__ __align__(1024) float g_Wt[DIM * DIM];  // W^T [n][k], tf32-rounded

// ---------------- helpers ----------------
DI uint32_t smem_u32(const void* p) {
    uint32_t a;
    asm("{ .reg .u64 t; cvta.to.shared.u64 t, %1; cvt.u32.u64 %0, t; }" : "=r"(a) : "l"(p));
    return a;
}
DI void cp16(uint32_t s, const void* g) {
    asm volatile("cp.async.cg.shared.global [%0], [%1], 16;" :: "r"(s), "l"(g) : "memory");
}
DI void cp_commit() { asm volatile("cp.async.commit_group;" ::: "memory"); }
template <int N> DI void cp_wait() {
    asm volatile("cp.async.wait_group %0;" :: "n"(N) : "memory");
}
DI uint32_t lds32(uint32_t a) {
    uint32_t v;
    asm volatile("ld.shared.b32 %0, [%1];" : "=r"(v) : "r"(a));
    return v;
}
DI uint32_t rna_tf32_u(uint32_t x) {
    uint32_t r;
    asm("cvt.rna.tf32.f32 %0, %1;" : "=r"(r) : "f"(__uint_as_float(x)));
    return r;
}
DI float rna_tf32(float x) {
    uint32_t r;
    asm("cvt.rna.tf32.f32 %0, %1;" : "=r"(r) : "f"(x));
    return __uint_as_float(r);
}
DI void mma_tf32(float* d, const uint32_t* a, const uint32_t* b) {
    asm volatile(
        "mma.sync.aligned.m16n8k8.row.col.f32.tf32.tf32.f32 "
        "{%0,%1,%2,%3}, {%4,%5,%6,%7}, {%8,%9}, {%0,%1,%2,%3};"
        : "+f"(d[0]), "+f"(d[1]), "+f"(d[2]), "+f"(d[3])
        : "r"(a[0]), "r"(a[1]), "r"(a[2]), "r"(a[3]), "r"(b[0]), "r"(b[1]));
}
DI uint32_t sw128(uint32_t off) { return off ^ ((off >> 3) & 0x70); }

// ---------------- SMEM layout ----------------
static constexpr int NST     = 4;
static constexpr int T_BYTES = 128 * 128;         // 128 rows x 32 fp32 (128B rows)
static constexpr int STAGE   = 2 * T_BYTES;       // A tile + B tile = 32 KB
static constexpr int DSMEM   = NST * STAGE;       // 128 KB

// ---------------- degree: g_dis[i] = rsqrt(1 + sum_j adj[i][j]) ------------
__global__ void __launch_bounds__(256) degree_kernel(const float* __restrict__ adj) {
    int i = blockIdx.x;
    const float4* row = reinterpret_cast<const float4*>(adj + (size_t)i * NN);
    float s = 0.f;
    for (int t = threadIdx.x; t < NN / 4; t += 256) {
        float4 v = row[t];
        s += (v.x + v.y) + (v.z + v.w);
    }
    for (int off = 16; off > 0; off >>= 1) s += __shfl_xor_sync(0xFFFFFFFFu, s, off);
    __shared__ float ws[8];
    if ((threadIdx.x & 31) == 0) ws[threadIdx.x >> 5] = s;
    __syncthreads();
    if (threadIdx.x == 0) {
        float t = 0.f;
        #pragma unroll
        for (int k = 0; k < 8; k++) t += ws[k];
        g_dis[i] = rsqrtf(t + 1.0f);
    }
}

// ---------------- prep: W^T rounded to tf32 --------------------------------
__global__ void __launch_bounds__(256) prep_w_kernel(const float* __restrict__ W) {
    int n = blockIdx.x, k = threadIdx.x;
    g_Wt[n * DIM + k] = rna_tf32(W[k * DIM + n]);
}

// ---------------- tf32 mma.sync GEMM: C[128x128] = A[128xK] @ B[128xK]^T ---
// EPI=0: A=x (lda=256, KT=8),   B=g_Wt.  C -> g_Mt[n][j] = rna(dis_j * acc)
// EPI=1: A=adj (lda=8192, KT=256), B=g_Mt. C -> out = relu(dis_i*(acc+Mt[n][i])+b[n])
template <int EPI>
__global__ void __launch_bounds__(256, 1)
gemm_k(const float* __restrict__ A, int lda, int KT,
       const float* __restrict__ bias, float* __restrict__ out) {
    const float* __restrict__ B = EPI ? (const float*)g_Mt : (const float*)g_Wt;
    const int ldb = EPI ? NN : DIM;

    extern __shared__ char smem[];
    const uint32_t sb = smem_u32(smem);
    const int tid = threadIdx.x, lane = tid & 31, wid = tid >> 5;
    const int wm = wid & 3, wn = wid >> 2;          // warp grid 4(M) x 2(N)
    const int mt = blockIdx.x, nt = blockIdx.y;
    const size_t mrow0 = (size_t)mt * 128;
    const size_t nrow0 = (size_t)nt * 128;

    float acc[2][8][4];
    #pragma unroll
    for (int mi = 0; mi < 2; mi++)
        #pragma unroll
        for (int ni = 0; ni < 8; ni++)
            #pragma unroll
            for (int r = 0; r < 4; r++) acc[mi][ni][r] = 0.f;

    // precomputed per-thread copy geometry: row = tid>>3 (+32/q), seg = tid&7
    const int crow = tid >> 3, cseg = tid & 7;
    const uint32_t sdst = sw128((uint32_t)(crow * 128 + cseg * 16));
    const float* gA = A + (mrow0 + crow) * (size_t)lda + cseg * 4;
    const float* gB = B + (nrow0 + crow) * (size_t)ldb + cseg * 4;
    const size_t stepA = 32ull * (size_t)lda;   // +32 rows
    const size_t stepB = 32ull * (size_t)ldb;

    auto load_stage = [&](int kt) {
        const int s = kt & (NST - 1);
        const uint32_t stA = sb + s * STAGE;
        const uint32_t stB = stA + T_BYTES;
        const int k0 = kt * 32;
        #pragma unroll
        for (int q = 0; q < 4; q++)
            cp16(stA + sdst + q * (32 * 128), gA + k0 + q * stepA);
        #pragma unroll
        for (int q = 0; q < 4; q++)
            cp16(stB + sdst + q * (32 * 128), gB + k0 + q * stepB);
        cp_commit();
    };

    // prologue: NST-1 stages in flight
    for (int p = 0; p < NST - 1 && p < KT; p++) load_stage(p);

    // fragment geometry
    const int arow_base = wm * 32 + (lane >> 2);     // + mi*16, +8
    const int brow_base = wn * 64 + (lane >> 2);     // + ni*8
    const int kcol = lane & 3;

    uint32_t bf[2][8][2];
    uint32_t af[2][2][4];

    auto load_frags = [&](uint32_t stA, uint32_t stB, int ks, int buf) {
        const int kb = ks * 8 + kcol;
        #pragma unroll
        for (int ni = 0; ni < 8; ni++) {
            int br = brow_base + ni * 8;
            bf[buf][ni][0] = lds32(stB + sw128((uint32_t)(br * 128 + kb * 4)));
            bf[buf][ni][1] = lds32(stB + sw128((uint32_t)(br * 128 + (kb + 4) * 4)));
        }
        #pragma unroll
        for (int mi = 0; mi < 2; mi++) {
            int ar = arow_base + mi * 16;
            af[buf][mi][0] = rna_tf32_u(lds32(stA + sw128((uint32_t)(ar * 128 + kb * 4))));
            af[buf][mi][1] = rna_tf32_u(lds32(stA + sw128((uint32_t)((ar + 8) * 128 + kb * 4))));
            af[buf][mi][2] = rna_tf32_u(lds32(stA + sw128((uint32_t)(ar * 128 + (kb + 4) * 4))));
            af[buf][mi][3] = rna_tf32_u(lds32(stA + sw128((uint32_t)((ar + 8) * 128 + (kb + 4) * 4))));
        }
    };

    for (int kt = 0; kt < KT; kt++) {
        cp_wait<NST - 2>();
        __syncthreads();
        // issue next stage's async loads NOW — hazard-safe: the barrier above
        // proves all warps finished compute(kt-1), whose stage == (kt+3)&3.
        if (kt + NST - 1 < KT) load_stage(kt + NST - 1);

        const int s = kt & (NST - 1);
        const uint32_t stA = sb + s * STAGE;
        const uint32_t stB = stA + T_BYTES;

        load_frags(stA, stB, 0, 0);
        #pragma unroll
        for (int ks = 0; ks < 4; ks++) {
            const int cur = ks & 1;
            if (ks < 3) load_frags(stA, stB, ks + 1, cur ^ 1);
            #pragma unroll
            for (int mi = 0; mi < 2; mi++)
                #pragma unroll
                for (int ni = 0; ni < 8; ni++)
                    mma_tf32(acc[mi][ni], af[cur][mi], bf[cur][ni]);
        }
    }

    // ---------------- epilogue ----------------
    #pragma unroll
    for (int mi = 0; mi < 2; mi++) {
        const int r0 = wm * 32 + mi * 16 + (lane >> 2);
        const size_t i0 = mrow0 + r0;
        const float dis0 = g_dis[i0], dis1 = g_dis[i0 + 8];
        #pragma unroll
        for (int ni = 0; ni < 8; ni++) {
            const int n = (int)nrow0 + wn * 64 + ni * 8 + (lane & 3) * 2;
            if (EPI == 0) {
                g_Mt[(size_t)n * NN + i0]           = rna_tf32(dis0 * acc[mi][ni][0]);
                g_Mt[(size_t)(n + 1) * NN + i0]     = rna_tf32(dis0 * acc[mi][ni][1]);
                g_Mt[(size_t)n * NN + i0 + 8]       = rna_tf32(dis1 * acc[mi][ni][2]);
                g_Mt[(size_t)(n + 1) * NN + i0 + 8] = rna_tf32(dis1 * acc[mi][ni][3]);
            } else {
                const float b0 = bias[n], b1 = bias[n + 1];
                float v0 = dis0 * (acc[mi][ni][0] + g_Mt[(size_t)n * NN + i0]) + b0;
                float v1 = dis0 * (acc[mi][ni][1] + g_Mt[(size_t)(n + 1) * NN + i0]) + b1;
                float v2 = dis1 * (acc[mi][ni][2] + g_Mt[(size_t)n * NN + i0 + 8]) + b0;
                float v3 = dis1 * (acc[mi][ni][3] + g_Mt[(size_t)(n + 1) * NN + i0 + 8]) + b1;
                float2 p0 = make_float2(v0 > 0.f ? v0 : 0.f, v1 > 0.f ? v1 : 0.f);
                float2 p1 = make_float2(v2 > 0.f ? v2 : 0.f, v3 > 0.f ? v3 : 0.f);
                *reinterpret_cast<float2*>(out + i0 * DIM + n)       = p0;
                *reinterpret_cast<float2*>(out + (i0 + 8) * DIM + n) = p1;
            }
        }
    }
}

// ---------------- launch ----------------
extern "C" void kernel_launch(void* const* d_in, const int* in_sizes, int n_in,
                              void* d_out, int out_size) {
    const float* x   = (const float*)d_in[0];
    const float* adj = (const float*)d_in[1];
    const float* W   = (const float*)d_in[2];
    const float* b   = (const float*)d_in[3];
    float* out = (float*)d_out;

    cudaFuncSetAttribute(gemm_k<0>, cudaFuncAttributeMaxDynamicSharedMemorySize, DSMEM);
    cudaFuncSetAttribute(gemm_k<1>, cudaFuncAttributeMaxDynamicSharedMemorySize, DSMEM);

    degree_kernel<<<NN, 256>>>(adj);
    prep_w_kernel<<<DIM, DIM>>>(W);
    gemm_k<0><<<dim3(NN / 128, 2), 256, DSMEM>>>(x, DIM, DIM / 32, nullptr, nullptr);
    gemm_k<1><<<dim3(NN / 128, 2), 256, DSMEM>>>(adj, NN, NN / 32, b, out);
}

// round 6
// speedup vs baseline: 1.4859x; 1.4859x over previous
#include <cuda_runtime.h>
#include <cuda_fp16.h>
#include <cstdint>

#define DI __device__ __forceinline__

static constexpr int NN  = 8192;
static constexpr int DIM = 256;

// ---------------- scratch (device globals; allocation forbidden) -----------
__device__ __align__(1024) __half g_adjh[(size_t)NN * NN];  // fp16 copy of adj (128 MB)
__device__ __align__(1024) float  g_dis[NN];                // rsqrt(1 + rowsum(adj))
__device__ __align__(1024) __half g_Mth[(size_t)DIM * NN];  // M^T [n][j] fp16
__device__ __align__(1024) __half g_xh[NN * DIM];           // x fp16
__device__ __align__(1024) __half g_Wh[DIM * DIM];          // W^T fp16

// ---------------- helpers ----------------
DI uint32_t h2_u32(__half2 h) {
    return *reinterpret_cast<uint32_t*>(&h);
}
DI uint32_t smem_u32(const void* p) {
    uint32_t a;
    asm("{ .reg .u64 t; cvta.to.shared.u64 t, %1; cvt.u32.u64 %0, t; }" : "=r"(a) : "l"(p));
    return a;
}
DI void cp16(uint32_t s, const void* g) {
    asm volatile("cp.async.cg.shared.global [%0], [%1], 16;" :: "r"(s), "l"(g) : "memory");
}
DI void cp_commit() { asm volatile("cp.async.commit_group;" ::: "memory"); }
template <int N> DI void cp_wait() {
    asm volatile("cp.async.wait_group %0;" :: "n"(N) : "memory");
}
DI uint32_t lds32(uint32_t a) {
    uint32_t v;
    asm volatile("ld.shared.b32 %0, [%1];" : "=r"(v) : "r"(a));
    return v;
}
DI void mma_f16(float* d, const uint32_t* a, const uint32_t* b) {
    asm volatile(
        "mma.sync.aligned.m16n8k16.row.col.f32.f16.f16.f32 "
        "{%0,%1,%2,%3}, {%4,%5,%6,%7}, {%8,%9}, {%0,%1,%2,%3};"
        : "+f"(d[0]), "+f"(d[1]), "+f"(d[2]), "+f"(d[3])
        : "r"(a[0]), "r"(a[1]), "r"(a[2]), "r"(a[3]), "r"(b[0]), "r"(b[1]));
}
DI uint32_t sw128(uint32_t off) { return off ^ ((off >> 3) & 0x70); }

// ---------------- SMEM layout ----------------
// Tiles: 128 rows x 64 fp16 (128 B rows, SW128). K per stage = 64.
static constexpr int NST     = 4;
static constexpr int T_BYTES = 128 * 128;          // 16 KB
static constexpr int STAGE   = 2 * T_BYTES;        // 32 KB
static constexpr int DSMEM   = NST * STAGE;        // 128 KB

// ------ degree + convert: g_dis[i] = rsqrt(1+rowsum), g_adjh = fp16(adj) ---
__global__ void __launch_bounds__(256) degree_kernel(const float* __restrict__ adj) {
    const int i = blockIdx.x;
    const float4* row = reinterpret_cast<const float4*>(adj + (size_t)i * NN);
    uint4* orow = reinterpret_cast<uint4*>(g_adjh + (size_t)i * NN);
    float s = 0.f;
    for (int t = threadIdx.x; t < NN / 8; t += 256) {
        float4 v0 = row[2 * t], v1 = row[2 * t + 1];
        s += ((v0.x + v0.y) + (v0.z + v0.w)) + ((v1.x + v1.y) + (v1.z + v1.w));
        uint4 o;
        o.x = h2_u32(__floats2half2_rn(v0.x, v0.y));
        o.y = h2_u32(__floats2half2_rn(v0.z, v0.w));
        o.z = h2_u32(__floats2half2_rn(v1.x, v1.y));
        o.w = h2_u32(__floats2half2_rn(v1.z, v1.w));
        orow[t] = o;
    }
    for (int off = 16; off > 0; off >>= 1) s += __shfl_xor_sync(0xFFFFFFFFu, s, off);
    __shared__ float ws[8];
    if ((threadIdx.x & 31) == 0) ws[threadIdx.x >> 5] = s;
    __syncthreads();
    if (threadIdx.x == 0) {
        float t = 0.f;
        #pragma unroll
        for (int k = 0; k < 8; k++) t += ws[k];
        g_dis[i] = rsqrtf(t + 1.0f);
    }
}

// ---------------- prep: x -> fp16, W^T -> fp16 -----------------------------
__global__ void __launch_bounds__(256) prep_x_kernel(const float4* __restrict__ x) {
    int total = NN * DIM / 8;
    for (int t = blockIdx.x * blockDim.x + threadIdx.x; t < total; t += gridDim.x * blockDim.x) {
        float4 v0 = x[2 * t], v1 = x[2 * t + 1];
        uint4 o;
        o.x = h2_u32(__floats2half2_rn(v0.x, v0.y));
        o.y = h2_u32(__floats2half2_rn(v0.z, v0.w));
        o.z = h2_u32(__floats2half2_rn(v1.x, v1.y));
        o.w = h2_u32(__floats2half2_rn(v1.z, v1.w));
        reinterpret_cast<uint4*>(g_xh)[t] = o;
    }
}
__global__ void __launch_bounds__(256) prep_w_kernel(const float* __restrict__ W) {
    int n = blockIdx.x, k = threadIdx.x;
    g_Wh[n * DIM + k] = __float2half_rn(W[k * DIM + n]);
}

// -------- fp16 mma.sync GEMM: C[128x128] = A[128xK] @ B[128xK]^T -----------
// EPI=0: A=g_xh (lda=256, KT=4),     B=g_Wh.  C -> g_Mth[n][j] = h(dis_j*acc)
// EPI=1: A=g_adjh (lda=8192,KT=128), B=g_Mth. C -> out=relu(dis_i*(acc+Mt[n][i])+b[n])
template <int EPI>
__global__ void __launch_bounds__(256, 1)
gemm_k(const __half* __restrict__ A, int lda, int KT,
       const float* __restrict__ bias, float* __restrict__ out) {
    const __half* __restrict__ B = EPI ? (const __half*)g_Mth : (const __half*)g_Wh;
    const int ldb = EPI ? NN : DIM;

    extern __shared__ char smem[];
    const uint32_t sb = smem_u32(smem);
    const int tid = threadIdx.x, lane = tid & 31, wid = tid >> 5;
    const int wm = wid & 3, wn = wid >> 2;          // warp grid 4(M) x 2(N)
    const size_t mrow0 = (size_t)blockIdx.x * 128;
    const size_t nrow0 = (size_t)blockIdx.y * 128;

    float acc[2][8][4];
    #pragma unroll
    for (int mi = 0; mi < 2; mi++)
        #pragma unroll
        for (int ni = 0; ni < 8; ni++)
            #pragma unroll
            for (int r = 0; r < 4; r++) acc[mi][ni][r] = 0.f;

    // copy geometry: per tile 1024 x 16B chunks; chunk = row(128B) x seg(16B)
    const int crow = tid >> 3, cseg = tid & 7;
    const uint32_t sdst = sw128((uint32_t)(crow * 128 + cseg * 16));
    const __half* gA = A + (mrow0 + crow) * (size_t)lda + cseg * 8;
    const __half* gB = B + (nrow0 + crow) * (size_t)ldb + cseg * 8;
    const size_t stepA = 32ull * (size_t)lda;
    const size_t stepB = 32ull * (size_t)ldb;

    auto load_stage = [&](int kt) {
        const int s = kt & (NST - 1);
        const uint32_t stA = sb + s * STAGE;
        const uint32_t stB = stA + T_BYTES;
        const int k0 = kt * 64;
        #pragma unroll
        for (int q = 0; q < 4; q++)
            cp16(stA + sdst + q * (32 * 128), gA + k0 + q * stepA);
        #pragma unroll
        for (int q = 0; q < 4; q++)
            cp16(stB + sdst + q * (32 * 128), gB + k0 + q * stepB);
        cp_commit();
    };

    for (int p = 0; p < NST - 1 && p < KT; p++) load_stage(p);

    // fragment geometry (m16n8k16, fp16)
    const int arow_base = wm * 32 + (lane >> 2);     // + mi*16, +8
    const int brow_base = wn * 64 + (lane >> 2);     // + ni*8
    const int kbyte = (lane & 3) * 4;                // byte offset of k-pair

    for (int kt = 0; kt < KT; kt++) {
        cp_wait<NST - 2>();
        __syncthreads();
        const int s = kt & (NST - 1);
        const uint32_t stA = sb + s * STAGE;
        const uint32_t stB = stA + T_BYTES;

        #pragma unroll
        for (int ks = 0; ks < 4; ks++) {
            const int kb = ks * 32 + kbyte;          // byte col of this k16 step
            uint32_t bf[8][2];
            #pragma unroll
            for (int ni = 0; ni < 8; ni++) {
                int br = brow_base + ni * 8;
                bf[ni][0] = lds32(stB + sw128((uint32_t)(br * 128 + kb)));
                bf[ni][1] = lds32(stB + sw128((uint32_t)(br * 128 + kb + 16)));
            }
            #pragma unroll
            for (int mi = 0; mi < 2; mi++) {
                int ar = arow_base + mi * 16;
                uint32_t af[4];
                af[0] = lds32(stA + sw128((uint32_t)(ar * 128 + kb)));
                af[1] = lds32(stA + sw128((uint32_t)((ar + 8) * 128 + kb)));
                af[2] = lds32(stA + sw128((uint32_t)(ar * 128 + kb + 16)));
                af[3] = lds32(stA + sw128((uint32_t)((ar + 8) * 128 + kb + 16)));
                #pragma unroll
                for (int ni = 0; ni < 8; ni++) mma_f16(acc[mi][ni], af, bf[ni]);
            }
        }
        __syncthreads();
        if (kt + NST - 1 < KT) load_stage(kt + NST - 1);
    }

    // ---------------- epilogue ----------------
    #pragma unroll
    for (int mi = 0; mi < 2; mi++) {
        const int r0 = wm * 32 + mi * 16 + (lane >> 2);
        const size_t i0 = mrow0 + r0;
        const float dis0 = g_dis[i0], dis1 = g_dis[i0 + 8];
        #pragma unroll
        for (int ni = 0; ni < 8; ni++) {
            const int n = (int)nrow0 + wn * 64 + ni * 8 + (lane & 3) * 2;
            if (EPI == 0) {
                g_Mth[(size_t)n * NN + i0]           = __float2half_rn(dis0 * acc[mi][ni][0]);
                g_Mth[(size_t)(n + 1) * NN + i0]     = __float2half_rn(dis0 * acc[mi][ni][1]);
                g_Mth[(size_t)n * NN + i0 + 8]       = __float2half_rn(dis1 * acc[mi][ni][2]);
                g_Mth[(size_t)(n + 1) * NN + i0 + 8] = __float2half_rn(dis1 * acc[mi][ni][3]);
            } else {
                const float b0 = bias[n], b1 = bias[n + 1];
                float m0 = __half2float(g_Mth[(size_t)n * NN + i0]);
                float m1 = __half2float(g_Mth[(size_t)(n + 1) * NN + i0]);
                float m2 = __half2float(g_Mth[(size_t)n * NN + i0 + 8]);
                float m3 = __half2float(g_Mth[(size_t)(n + 1) * NN + i0 + 8]);
                float v0 = dis0 * (acc[mi][ni][0] + m0) + b0;
                float v1 = dis0 * (acc[mi][ni][1] + m1) + b1;
                float v2 = dis1 * (acc[mi][ni][2] + m2) + b0;
                float v3 = dis1 * (acc[mi][ni][3] + m3) + b1;
                float2 p0 = make_float2(v0 > 0.f ? v0 : 0.f, v1 > 0.f ? v1 : 0.f);
                float2 p1 = make_float2(v2 > 0.f ? v2 : 0.f, v3 > 0.f ? v3 : 0.f);
                *reinterpret_cast<float2*>(out + i0 * DIM + n)       = p0;
                *reinterpret_cast<float2*>(out + (i0 + 8) * DIM + n) = p1;
            }
        }
    }
}

// ---------------- launch ----------------
extern "C" void kernel_launch(void* const* d_in, const int* in_sizes, int n_in,
                              void* d_out, int out_size) {
    const float* x   = (const float*)d_in[0];
    const float* adj = (const float*)d_in[1];
    const float* W   = (const float*)d_in[2];
    const float* b   = (const float*)d_in[3];
    float* out = (float*)d_out;

    cudaFuncSetAttribute(gemm_k<0>, cudaFuncAttributeMaxDynamicSharedMemorySize, DSMEM);
    cudaFuncSetAttribute(gemm_k<1>, cudaFuncAttributeMaxDynamicSharedMemorySize, DSMEM);

    degree_kernel<<<NN, 256>>>(adj);
    prep_x_kernel<<<512, 256>>>((const float4*)x);
    prep_w_kernel<<<DIM, DIM>>>(W);

    __half* xh;   cudaGetSymbolAddress((void**)&xh,  g_xh);
    __half* adjh; cudaGetSymbolAddress((void**)&adjh, g_adjh);

    gemm_k<0><<<dim3(NN / 128, 2), 256, DSMEM>>>(xh, DIM, DIM / 64, nullptr, nullptr);
    gemm_k<1><<<dim3(NN / 128, 2), 256, DSMEM>>>(adjh, NN, NN / 64, b, out);
}